// round 17
// baseline (speedup 1.0000x reference)
#include <cuda_runtime.h>

typedef unsigned long long ull;

__device__ __forceinline__ ull pk2(float a, float b) {
    ull r; asm("mov.b64 %0,{%1,%2};" : "=l"(r) : "f"(a), "f"(b)); return r;
}
__device__ __forceinline__ void upk2(ull v, float& a, float& b) {
    asm("mov.b64 {%0,%1},%2;" : "=f"(a), "=f"(b) : "l"(v));
}
__device__ __forceinline__ ull mul2(ull a, ull b) {
    ull r; asm("mul.rn.f32x2 %0,%1,%2;" : "=l"(r) : "l"(a), "l"(b)); return r;
}
__device__ __forceinline__ ull add2(ull a, ull b) {
    ull r; asm("add.rn.f32x2 %0,%1,%2;" : "=l"(r) : "l"(a), "l"(b)); return r;
}
__device__ __forceinline__ ull fma2(ull a, ull b, ull c) {
    ull r; asm("fma.rn.f32x2 %0,%1,%2,%3;" : "=l"(r) : "l"(a), "l"(b), "l"(c)); return r;
}

extern __shared__ ull sgrid[];  // NG * 10 ull: 8 dup'd grid coords, dup'd -norm, pad

// Near-tie resolution (rare path). ya2pk = packed DOUBLED magnitudes; lane
// selects P(lo)/M(hi). fp32 walk (bit-identical to mainloop scores), exact
// double scoring only for candidates within thr of the fp32 best. Returns
// the true double argmax, first-index ties — same result as a full double
// rescan (doubling commutes exactly with every rounding in both precisions).
__device__ __noinline__ int rescan_shortlist(const ull* ya2pk, int hi,
                                             float bbest, float thr, int NG)
{
    float y[8];
    #pragma unroll
    for (int i = 0; i < 8; i++) {
        float lo, hb; upk2(ya2pk[i], lo, hb);
        y[i] = hi ? hb : lo;
    }
    const float* sg = (const float*)sgrid;   // lo lanes of packed layout
    float cutoff = __fadd_rn(bbest, -thr);
    double yd[8];
    #pragma unroll
    for (int i = 0; i < 8; i++) yd[i] = (double)y[i];
    double best_d = -1e300;
    int q = 0;
    for (int g = 0; g < NG; g++) {
        const float* row = sg + g * 20;      // stride 10 ull = 20 floats
        float s = __fmul_rn(y[0], row[0]);
        s = __fmaf_rn(y[1], row[2],  s);
        s = __fmaf_rn(y[2], row[4],  s);
        s = __fmaf_rn(y[3], row[6],  s);
        s = __fmaf_rn(y[4], row[8],  s);
        s = __fmaf_rn(y[5], row[10], s);
        s = __fmaf_rn(y[6], row[12], s);
        s = __fmaf_rn(y[7], row[14], s);
        s = __fadd_rn(s, row[16]);           // + (-norm); operands pre-doubled
        if (s >= cutoff) {
            double sd = 0.0;
            #pragma unroll
            for (int i = 0; i < 8; i++)
                sd = fma(yd[i], (double)row[2 * i], sd);
            sd = sd + (double)row[16];
            if (sd > best_d) { best_d = sd; q = g; }
        }
    }
    return q;
}

__global__ __launch_bounds__(512, 2)
void e8p_kernel(const float* __restrict__ X,
                const float* __restrict__ grid,
                const float* __restrict__ gnorm,
                const int* __restrict__ allcombo,
                float* __restrict__ out,
                int N, int NG, int ac_stride)
{
    for (int g = threadIdx.x; g < NG; g += blockDim.x) {
        const float* gp = grid + g * 8;
        ull* sp = sgrid + g * 10;
        #pragma unroll
        for (int i = 0; i < 8; i++) { float v = gp[i]; sp[i] = pk2(v, v); }
        float nn = -gnorm[g];
        sp[8] = pk2(nn, nn);
        sp[9] = 0ull;
    }
    __syncthreads();

    int r = blockIdx.x * blockDim.x + threadIdx.x;
    if (r >= N) return;

    // Build packed DOUBLED magnitudes ya2 = 2*|y| (sign-folded). Doubling is
    // exact, so score = ya2.g - norm is bit-identical to 2*(ya.g) - norm
    // computed the R16 way. x[] is NOT kept live across the mainloop
    // (reloaded in the epilogue) to eliminate register spills.
    unsigned nbP = 0, nbM = 0;
    ull ya2[8];
    {
        const float4* xp = (const float4*)(X + (size_t)r * 8);
        float4 xa = xp[0], xb = xp[1];
        float x[8] = {xa.x, xa.y, xa.z, xa.w, xb.x, xb.y, xb.z, xb.w};
        float yP[8], yM[8];
        #pragma unroll
        for (int i = 0; i < 8; i++) {
            yP[i] = __fadd_rn(x[i], 0.25f);
            yM[i] = __fadd_rn(x[i], -0.25f);
            if (yP[i] < 0.f) nbP |= 1u << i;
            if (yM[i] < 0.f) nbM |= 1u << i;
        }
        unsigned oddP = __popc(nbP) & 1u;
        unsigned oddM = __popc(nbM) & 1u;
        #pragma unroll
        for (int i = 0; i < 8; i++) {
            float aP = fabsf(yP[i]), aM = fabsf(yM[i]);
            if (i == 0) {
                if (oddP) aP = -aP;
                if (oddM) aM = -aM;
            }
            ull t = pk2(aP, aM);
            ya2[i] = add2(t, t);   // exact doubling
        }
    }

    // Packed fp32 argmax of ya2.g - |g|^2 with runner-up tracking.
    // 9 packed fma-pipe ops per candidate.
    float bP = -3.4e38f, bM = -3.4e38f;
    float b2P = -3.4e38f, b2M = -3.4e38f;
    int qP = 0, qM = 0;
    #pragma unroll 4
    for (int g = 0; g < NG; g++) {
        const ulonglong2* p = (const ulonglong2*)(sgrid + g * 10);
        ulonglong2 c0 = p[0], c1 = p[1], c2 = p[2], c3 = p[3], c4 = p[4];
        ull s = mul2(ya2[0], c0.x);
        s = fma2(ya2[1], c0.y, s);
        s = fma2(ya2[2], c1.x, s);
        s = fma2(ya2[3], c1.y, s);
        s = fma2(ya2[4], c2.x, s);
        s = fma2(ya2[5], c2.y, s);
        s = fma2(ya2[6], c3.x, s);
        s = fma2(ya2[7], c3.y, s);
        s = add2(s, c4.x);     // + (-norm); doubling already folded into ya2
        float sp, sm;
        upk2(s, sp, sm);
        if (sp > bP) { b2P = bP; bP = sp; qP = g; }
        else if (sp > b2P) { b2P = sp; }
        if (sm > bM) { b2M = bM; bM = sm; qM = g; }
        else if (sm > b2M) { b2M = sm; }
    }
    // Near-tie? Resolve exactly (identical thresholds/semantics as R16).
    float thrP = 1e-4f * fmaxf(1.f, fabsf(bP));
    float thrM = 1e-4f * fmaxf(1.f, fabsf(bM));
    if (__fadd_rn(bP, -b2P) < thrP)
        qP = rescan_shortlist(ya2, 0, bP, thrP, NG);
    if (__fadd_rn(bM, -b2M) < thrM)
        qM = rescan_shortlist(ya2, 1, bM, thrM, NG);

    // Epilogue. Reload X (L2-hot) instead of keeping x live in registers.
    const float4* xp = (const float4*)(X + (size_t)r * 8);
    float4 xa = xp[0], xb = xp[1];
    float x[8] = {xa.x, xa.y, xa.z, xa.w, xb.x, xb.y, xb.z, xb.w};

    unsigned oddP = __popc(nbP) & 1u;
    unsigned oddM = __popc(nbM) & 1u;
    unsigned mbP = nbP ^ oddP;
    unsigned mbM = nbM ^ oddM;

    // idx_map[mint] == mint >> 1 (one even-parity byte per consecutive pair).
    unsigned mintP = __brev(mbP) >> 24;
    unsigned mintM = __brev(mbM) >> 24;
    int rowP = (int)(mintP >> 1);
    int rowM = (int)(mintM >> 1);

    int realP = allcombo[rowP * ac_stride + qP];
    int realM = allcombo[rowM * ac_stride + qM];

    const float* gP = grid + qP * 8;
    const float* gM = grid + qM * 8;
    float vP[8], vM[8];
    // Exact-double error sums (validated bit-exact in R11/R14/R16).
    double eP2 = 0.0, eM2 = 0.0;
    #pragma unroll
    for (int i = 0; i < 8; i++) {
        float yPi = __fadd_rn(x[i], 0.25f);
        float yMi = __fadd_rn(x[i], -0.25f);
        float gvP = gP[i];
        if ((mbP >> i) & 1u) gvP = -gvP;
        vP[i] = gvP;
        double dP = (double)yPi - (double)gvP;
        eP2 = fma(dP, dP, eP2);
        float gvM = gM[i];
        if ((mbM >> i) & 1u) gvM = -gvM;
        vM[i] = gvM;
        double dM = (double)yMi - (double)gvM;
        eM2 = fma(dM, dM, eM2);
    }
    float eP = __fsqrt_rn((float)eP2);
    float eM = __fsqrt_rn((float)eM2);
    bool which = eP < eM;

    float ov[8];
    #pragma unroll
    for (int i = 0; i < 8; i++)
        ov[i] = which ? __fadd_rn(vP[i], -0.25f) : __fadd_rn(vM[i], 0.25f);

    float4* outp = (float4*)(out + (size_t)r * 8);
    outp[0] = make_float4(ov[0], ov[1], ov[2], ov[3]);
    outp[1] = make_float4(ov[4], ov[5], ov[6], ov[7]);

    // Output 1: grid_idx_map[k] == int16(k - 32768), widened to f32 at
    // element offset 8N (validated in R14/R16).
    int sel = which ? (realP + 32768) : realM;
    sel &= 0xFFFF;
    short iv = (short)(sel - 32768);
    out[(size_t)N * 8 + r] = (float)iv;
}

extern "C" void kernel_launch(void* const* d_in, const int* in_sizes, int n_in,
                              void* d_out, int out_size)
{
    const float* X        = (const float*)d_in[0];
    const float* grid     = (const float*)d_in[1];
    const float* gnorm    = (const float*)d_in[2];
    const int*   allcombo = (const int*)d_in[3];

    int N  = in_sizes[0] / 8;
    int NG = in_sizes[2];
    int ac_stride = in_sizes[3] / 128;   // allcombo_idx is (128, stride)

    size_t smem = (size_t)NG * 10 * sizeof(unsigned long long);
    cudaFuncSetAttribute(e8p_kernel, cudaFuncAttributeMaxDynamicSharedMemorySize,
                         (int)smem);

    int threads = 512;
    int blocks = (N + threads - 1) / threads;
    e8p_kernel<<<blocks, threads, smem>>>(X, grid, gnorm, allcombo,
                                          (float*)d_out, N, NG, ac_stride);
}